// round 14
// baseline (speedup 1.0000x reference)
#include <cuda_runtime.h>
#include <math.h>

#define B_ 64
#define T_ 1024
#define I_ 128
#define H_ 512

#define CLUSTER 16
#define GRID_SCAN 128
#define NT 256

// ---------------- device scratch (no allocations allowed) -------------------
__device__ float g_xp[B_ * T_ * H_];        // x @ W_in + b_in        [B,T,512]
__device__ float g_xq[B_ * T_ * (H_ / 2)];  // x @ W_eff + b_eff      [B,T,256]
__device__ float g_hs[B_ * T_ * H_];        // all hidden states      [B,T,512]
__device__ float g_weff[I_ * (H_ / 2)];     // W_in @ W_tau1[:512]    [128,256]
__device__ float g_beff[H_ / 2];            // b_in @ W1x + b_tau1    [256]

// ---------------- scan SMEM layout (floats) ---------------------------------
#define H_S   516
#define W1_S  516
#define WR_S  516
#define W2_S  260
#define Z1_S  260
#define S1_S  129     // A1 partial stride (odd -> conflict-free scalar access)
#define D_S   36      // drive/tau buffer stride: bank = row*4+col, distinct
#define HBUF  (8 * H_S)                       // 4128 floats per h buffer
constexpr int P_H0   = 0;                     // [8][516]  h buffer 0
constexpr int P_H1   = HBUF;                  // [8][516]  h buffer 1
constexpr int P_WT1  = 2 * HBUF;              // [16][516] W_tau1 h-part ^T
constexpr int P_WREC = P_WT1 + 16 * W1_S;     // [32][516] W_rec rows
constexpr int P_WT2  = P_WREC + 32 * WR_S;    // [32][260] W_tau2 ^T
constexpr int P_Z1   = P_WT2 + 32 * W2_S;     // [8][260]  full z1 (DSMEM-filled)
constexpr int P_SCR  = P_Z1 + 8 * Z1_S;       // [8256]    A1 partials (64*129)
constexpr int P_DRV  = P_SCR + 8256;          // [8][36]   drive / tau results
constexpr int P_B1   = P_DRV + 8 * D_S;       // [16]
constexpr int P_BIAS = P_B1 + 16;             // [32]
constexpr int P_B2   = P_BIAS + 32;           // [32]
constexpr int SCAN_FLOATS = P_B2 + 32;
constexpr int SCAN_SMEM = SCAN_FLOATS * 4;    // ~208 KB

constexpr int XP_SMEM = (64 * 132 + 128 * 68) * 4;  // ~68.6 KB

// ---------------- helpers ----------------------------------------------------
__device__ __forceinline__ void fma2(unsigned long long& d,
                                     unsigned long long a,
                                     unsigned long long b) {
    asm("fma.rn.f32x2 %0, %1, %2, %0;" : "+l"(d) : "l"(a), "l"(b));
}
__device__ __forceinline__ float pair_sum(unsigned long long v) {
    return __uint_as_float((unsigned)v) + __uint_as_float((unsigned)(v >> 32));
}
__device__ __forceinline__ void st_cluster(unsigned addr, unsigned rank, float v) {
    unsigned ra;
    asm volatile("mapa.shared::cluster.u32 %0, %1, %2;" : "=r"(ra) : "r"(addr), "r"(rank));
    asm volatile("st.shared::cluster.f32 [%0], %1;" :: "r"(ra), "f"(v) : "memory");
}
// In-warp transpose-reduce: lane L enters with v[0..31] (v[j] = partial of
// output j); exits with v[0] = fully-reduced output L.
__device__ __forceinline__ float warp_transpose_reduce(float* v, int lane) {
#pragma unroll
    for (int s = 16; s >= 1; s >>= 1) {
        const bool up = (lane & s) != 0;
#pragma unroll
        for (int j = 0; j < s; j++) {
            float keep = up ? v[j + s] : v[j];
            float send = up ? v[j] : v[j + s];
            float recv = __shfl_xor_sync(0xffffffff, send, s);
            v[j] = keep + recv;
        }
    }
    return v[0];
}
#define CL_ARRIVE() asm volatile("barrier.cluster.arrive.aligned;" ::: "memory")
#define CL_WAIT()   asm volatile("barrier.cluster.wait.aligned;"   ::: "memory")
#define CLUSTER_SYNC() do { CL_ARRIVE(); CL_WAIT(); } while (0)

// ---------------- W_eff = W_in @ W_tau1[:512,:] ------------------------------
__global__ void __launch_bounds__(256) weff_gemm(const float* __restrict__ Win,
                                                 const float* __restrict__ Wt1) {
    __shared__ float sa[64 * 68];
    __shared__ float sb[64 * 68];
    const int tid = threadIdx.x;
    const int n0 = blockIdx.x * 64, m0 = blockIdx.y * 64;
    const int ty = tid >> 4, tx = tid & 15;
    float acc[4][4];
#pragma unroll
    for (int i = 0; i < 4; i++)
#pragma unroll
        for (int j = 0; j < 4; j++) acc[i][j] = 0.f;

    for (int kt = 0; kt < 512; kt += 64) {
        for (int f = tid; f < 64 * 16; f += 256) {
            int r = f >> 4, q = (f & 15) << 2;
            *(float4*)&sa[r * 68 + q] = *(const float4*)&Win[(size_t)(m0 + r) * 512 + kt + q];
            *(float4*)&sb[r * 68 + q] = *(const float4*)&Wt1[(size_t)(kt + r) * 256 + n0 + q];
        }
        __syncthreads();
#pragma unroll 8
        for (int k = 0; k < 64; k++) {
            float a[4];
#pragma unroll
            for (int i = 0; i < 4; i++) a[i] = sa[(ty * 4 + i) * 68 + k];
            float4 w = *(const float4*)&sb[k * 68 + tx * 4];
#pragma unroll
            for (int i = 0; i < 4; i++) {
                acc[i][0] += a[i] * w.x; acc[i][1] += a[i] * w.y;
                acc[i][2] += a[i] * w.z; acc[i][3] += a[i] * w.w;
            }
        }
        __syncthreads();
    }
#pragma unroll
    for (int i = 0; i < 4; i++) {
        float4 r;
        r.x = acc[i][0]; r.y = acc[i][1]; r.z = acc[i][2]; r.w = acc[i][3];
        *(float4*)&g_weff[(size_t)(m0 + ty * 4 + i) * 256 + n0 + tx * 4] = r;
    }
}

// ---------------- b_eff = b_in @ W1x + b_tau1 --------------------------------
__global__ void __launch_bounds__(64) beff_kernel(const float* __restrict__ b_in,
                                                  const float* __restrict__ Wt1,
                                                  const float* __restrict__ b_tau1) {
    __shared__ float red[64];
    const int c = blockIdx.x, lane = threadIdx.x;
    float p = 0.f;
    for (int k = lane; k < 512; k += 64) p += b_in[k] * Wt1[(size_t)k * 256 + c];
    red[lane] = p;
    __syncthreads();
    if (lane < 32) {
        float v = red[lane] + red[lane + 32];
        v += __shfl_xor_sync(0xffffffff, v, 16);
        v += __shfl_xor_sync(0xffffffff, v, 8);
        v += __shfl_xor_sync(0xffffffff, v, 4);
        v += __shfl_xor_sync(0xffffffff, v, 2);
        v += __shfl_xor_sync(0xffffffff, v, 1);
        if (lane == 0) g_beff[c] = v + b_tau1[c];
    }
}

// ---------------- generic projection: out = x @ W + b -----------------------
template <int NCOLS>
__global__ void __launch_bounds__(256) proj_gemm(const float* __restrict__ x,
                                                 const float* __restrict__ W,
                                                 const float* __restrict__ bvec,
                                                 float* __restrict__ outp) {
    extern __shared__ float sm[];
    float* sx = sm;                 // [64][132]
    float* sw = sm + 64 * 132;      // [128][68]
    const int tid = threadIdx.x;
    const int n0 = blockIdx.x * 64;
    const int r0 = blockIdx.y * 64;

    for (int f = tid; f < 64 * 32; f += 256) {
        int row = f >> 5, kq = (f & 31) << 2;
        *(float4*)(sx + row * 132 + kq) =
            *(const float4*)(x + (size_t)(r0 + row) * I_ + kq);
    }
    for (int f = tid; f < 128 * 16; f += 256) {
        int k = f >> 4, nq = (f & 15) << 2;
        *(float4*)(sw + k * 68 + nq) =
            *(const float4*)(W + (size_t)k * NCOLS + n0 + nq);
    }
    __syncthreads();

    const int ty = tid >> 4, tx = tid & 15;
    float acc[4][4];
#pragma unroll
    for (int i = 0; i < 4; i++)
#pragma unroll
        for (int j = 0; j < 4; j++) acc[i][j] = 0.f;

#pragma unroll 8
    for (int k = 0; k < 128; k++) {
        float a[4];
#pragma unroll
        for (int i = 0; i < 4; i++) a[i] = sx[(ty * 4 + i) * 132 + k];
        float4 w = *(const float4*)(sw + k * 68 + tx * 4);
#pragma unroll
        for (int i = 0; i < 4; i++) {
            acc[i][0] += a[i] * w.x; acc[i][1] += a[i] * w.y;
            acc[i][2] += a[i] * w.z; acc[i][3] += a[i] * w.w;
        }
    }

    float4 bv = *(const float4*)(bvec + n0 + tx * 4);
#pragma unroll
    for (int i = 0; i < 4; i++) {
        float4 r;
        r.x = acc[i][0] + bv.x; r.y = acc[i][1] + bv.y;
        r.z = acc[i][2] + bv.z; r.w = acc[i][3] + bv.w;
        *(float4*)(outp + (size_t)(r0 + ty * 4 + i) * NCOLS + n0 + tx * 4) = r;
    }
}

// ---------------- persistent clustered scan ----------------------------------
__global__ void __launch_bounds__(NT, 1) __cluster_dims__(CLUSTER, 1, 1)
scan_kernel(const float* __restrict__ W_rec, const float* __restrict__ bias,
            const float* __restrict__ W_tau1, const float* __restrict__ b_tau1,
            const float* __restrict__ W_tau2, const float* __restrict__ b_tau2) {
    extern __shared__ float sm[];
    const int tid = threadIdx.x;
    const int cid = blockIdx.x & (CLUSTER - 1);
    const int bg  = blockIdx.x >> 4;
    const int r0  = bg * 8;
    const int hc0 = cid * 32;
    const int zc0 = cid * 16;
    const unsigned sbase = (unsigned)__cvta_generic_to_shared(sm);

    // ---- one-time weight staging ----
    for (int e = tid; e < 16 * 512; e += NT) {     // W_tau1 h-part, transposed
        int c = e >> 9, k = e & 511;
        sm[P_WT1 + c * W1_S + k] = __ldg(&W_tau1[(size_t)(512 + k) * 256 + zc0 + c]);
    }
    for (int e = tid; e < 32 * 512; e += NT) {     // W_rec rows
        int c = e >> 9, k = e & 511;
        sm[P_WREC + c * WR_S + k] = __ldg(&W_rec[(size_t)(hc0 + c) * 512 + k]);
    }
    for (int e = tid; e < 32 * 256; e += NT) {     // W_tau2 transposed
        int c = e >> 8, k = e & 255;
        sm[P_WT2 + c * W2_S + k] = __ldg(&W_tau2[(size_t)k * 512 + hc0 + c]);
    }
    if (tid < 16) sm[P_B1 + tid]   = b_tau1[zc0 + tid];
    if (tid < 32) sm[P_BIAS + tid] = bias[hc0 + tid];
    if (tid < 32) sm[P_B2 + tid]   = b_tau2[hc0 + tid];
    // zero both h buffers
    for (int e = tid; e < 2 * HBUF; e += NT) sm[e] = 0.f;
    __syncthreads();

    // ---- register-resident weights ----
    // A2/B1 geometry: sA = lane (32 k-splits), tcA = warp*4 (4 cols)
    const int sA = tid & 31;
    const int tcA = (tid >> 5) * 4;
    unsigned long long wrec[4][4][2];   // A2: k = sA*4 + j*128, j<4
#pragma unroll
    for (int j = 0; j < 4; j++)
#pragma unroll
        for (int c = 0; c < 4; c++) {
            double2 wv = *(const double2*)&sm[P_WREC + (tcA + c) * WR_S + sA * 4 + j * 128];
            wrec[j][c][0] = __double_as_longlong(wv.x);
            wrec[j][c][1] = __double_as_longlong(wv.y);
        }
    unsigned long long wt2[2][4][2];    // B1: k = sA*4 + j*128, j<2
#pragma unroll
    for (int j = 0; j < 2; j++)
#pragma unroll
        for (int c = 0; c < 4; c++) {
            double2 wv = *(const double2*)&sm[P_WT2 + (tcA + c) * W2_S + sA * 4 + j * 128];
            wt2[j][c][0] = __double_as_longlong(wv.x);
            wt2[j][c][1] = __double_as_longlong(wv.y);
        }
    // A1 geometry: sZ = tid&63 (64 k-splits), tcZ = (tid>>6)*4 (4 of 16 cols)
    const int sZ = tid & 63;
    const int tcZ = (tid >> 6) * 4;
    unsigned long long wt1[2][4][2];    // A1: k = sZ*4 + j*256, j<2
#pragma unroll
    for (int j = 0; j < 2; j++)
#pragma unroll
        for (int c = 0; c < 4; c++) {
            double2 wv = *(const double2*)&sm[P_WT1 + (tcZ + c) * W1_S + sZ * 4 + j * 256];
            wt1[j][c][0] = __double_as_longlong(wv.x);
            wt1[j][c][1] = __double_as_longlong(wv.y);
        }

    CLUSTER_SYNC();

    const int rr = tid >> 5;      // 0..7 (h mapping)
    const int cc = tid & 31;      // 0..31
    const int zr = tid >> 4;      // z1 mapping (tid<128)
    const int zc = tid & 15;

    float xv  = __ldcg(&g_xp[((size_t)(r0 + rr) * T_) * H_ + hc0 + cc]);
    float xqv = 0.f;
    if (tid < 128)
        xqv = __ldcg(&g_xq[((size_t)(r0 + zr) * T_) * 256 + zc0 + zc]);

    float drv = 0.f;

    for (int t = 0; t < T_; t++) {
        const int pcur  = (t & 1) ? P_H1 : P_H0;
        const int pnext = (t & 1) ? P_H0 : P_H1;

        // ---- A1: z1 partials (8r x 16c, k=512), reg-W, 8r x 4c, S=64 ----
        {
            const float* ap = &sm[pcur];
            unsigned long long acc[32];
#pragma unroll
            for (int e = 0; e < 32; e++) acc[e] = 0ull;
#pragma unroll
            for (int j = 0; j < 2; j++) {
                const int k = sZ * 4 + j * 256;
#pragma unroll
                for (int i = 0; i < 8; i++) {
                    double2 av = *(const double2*)&ap[i * H_S + k];
                    unsigned long long a0 = __double_as_longlong(av.x);
                    unsigned long long a1 = __double_as_longlong(av.y);
#pragma unroll
                    for (int c = 0; c < 4; c++) {
                        fma2(acc[i * 4 + c], a0, wt1[j][c][0]);
                        fma2(acc[i * 4 + c], a1, wt1[j][c][1]);
                    }
                }
            }
#pragma unroll
            for (int i = 0; i < 8; i++)
#pragma unroll
                for (int c = 0; c < 4; c++)
                    sm[P_SCR + sZ * S1_S + i * 16 + tcZ + c] = pair_sum(acc[i * 4 + c]);
        }
        __syncthreads();

        // ---- z1 reduce (64 partials) + relu + scalar DSMEM push ----
        if (tid < 128) {
            float a0 = 0.f, a1 = 0.f;
#pragma unroll
            for (int s = 0; s < 64; s += 2) {
                a0 += sm[P_SCR + (s + 0) * S1_S + zr * 16 + zc];
                a1 += sm[P_SCR + (s + 1) * S1_S + zr * 16 + zc];
            }
            float z = sm[P_B1 + zc] + xqv + (a0 + a1);
            z = fmaxf(z, 0.f);
            unsigned a = sbase + (unsigned)(P_Z1 + zr * Z1_S + zc0 + zc) * 4u;
#pragma unroll
            for (unsigned rk = 0; rk < CLUSTER; rk++) st_cluster(a, rk, z);
        }
        __syncthreads();
        CL_ARRIVE();                       // (1) publish z1

        // ---- A2: drive (8r x 32c, k=512), reg-W + warp transpose-reduce ----
        {
            const float* ap = &sm[pcur];
            unsigned long long acc[32];
#pragma unroll
            for (int e = 0; e < 32; e++) acc[e] = 0ull;
#pragma unroll
            for (int j = 0; j < 4; j++) {
                const int k = sA * 4 + j * 128;
#pragma unroll
                for (int i = 0; i < 8; i++) {
                    double2 av = *(const double2*)&ap[i * H_S + k];
                    unsigned long long a0 = __double_as_longlong(av.x);
                    unsigned long long a1 = __double_as_longlong(av.y);
#pragma unroll
                    for (int c = 0; c < 4; c++) {
                        fma2(acc[i * 4 + c], a0, wrec[j][c][0]);
                        fma2(acc[i * 4 + c], a1, wrec[j][c][1]);
                    }
                }
            }
            float v[32];
#pragma unroll
            for (int e = 0; e < 32; e++) v[e] = pair_sum(acc[e]);
            float outv = warp_transpose_reduce(v, sA);
            // lane L holds output (row = L>>2, col = tcA + (L&3))
            sm[P_DRV + (sA >> 2) * D_S + tcA + (sA & 3)] = outv;
        }
        __syncthreads();

        // ---- drive -> tanh ----
        {
            float pre = xv + sm[P_BIAS + cc] + sm[P_DRV + rr * D_S + cc];
            float e2 = __expf(2.f * pre);
            drv = 1.f - 2.f / (e2 + 1.f);
        }
        CL_WAIT();                         // (1) z1 now resident in local P_Z1
        __syncthreads();                   // protect P_DRV reuse

        // ---- B1: tau (8r x 32c, k=256), reg-W + warp transpose-reduce ----
        {
            const float* ap = &sm[P_Z1];
            unsigned long long acc[32];
#pragma unroll
            for (int e = 0; e < 32; e++) acc[e] = 0ull;
#pragma unroll
            for (int j = 0; j < 2; j++) {
                const int k = sA * 4 + j * 128;
#pragma unroll
                for (int i = 0; i < 8; i++) {
                    double2 av = *(const double2*)&ap[i * Z1_S + k];
                    unsigned long long a0 = __double_as_longlong(av.x);
                    unsigned long long a1 = __double_as_longlong(av.y);
#pragma unroll
                    for (int c = 0; c < 4; c++) {
                        fma2(acc[i * 4 + c], a0, wt2[j][c][0]);
                        fma2(acc[i * 4 + c], a1, wt2[j][c][1]);
                    }
                }
            }
            float v[32];
#pragma unroll
            for (int e = 0; e < 32; e++) v[e] = pair_sum(acc[e]);
            float outv = warp_transpose_reduce(v, sA);
            sm[P_DRV + (sA >> 2) * D_S + tcA + (sA & 3)] = outv;
        }
        __syncthreads();

        // ---- B2: tau + Euler update + DSMEM h broadcast ----
        {
            float sv = sm[P_B2 + cc] + sm[P_DRV + rr * D_S + cc];
            float sig = 1.f / (1.f + __expf(-sv));
            float tau = 5.f + sig * 45.f;
            float hold = sm[pcur + rr * H_S + hc0 + cc];
            float hnew = hold + (drv - hold) / tau;
            unsigned a = sbase + (unsigned)(pnext + rr * H_S + hc0 + cc) * 4u;
#pragma unroll
            for (unsigned rk = 0; rk < CLUSTER; rk++) st_cluster(a, rk, hnew);
            __stcg(&g_hs[((size_t)(r0 + rr) * T_ + t) * H_ + hc0 + cc], hnew);
        }
        __syncthreads();
        CL_ARRIVE();                       // (2) publish h
        {
            int tn = (t + 1 < T_) ? t + 1 : t;          // prefetch next step
            xv = __ldcg(&g_xp[((size_t)(r0 + rr) * T_ + tn) * H_ + hc0 + cc]);
            if (tid < 128)
                xqv = __ldcg(&g_xq[((size_t)(r0 + zr) * T_ + tn) * 256 + zc0 + zc]);
        }
        CL_WAIT();                         // (2) h(t+1) resident in pnext
    }
}

// ---------------- out = hs @ W_out + b_out ----------------------------------
__global__ void __launch_bounds__(256) out_gemm(const float* __restrict__ W_out,
                                                const float* __restrict__ b_out,
                                                float* __restrict__ out) {
    __shared__ float sw[H_ * 10];
    __shared__ float sb[10];
    for (int e = threadIdx.x; e < H_ * 10; e += 256) sw[e] = W_out[e];
    if (threadIdx.x < 10) sb[threadIdx.x] = b_out[threadIdx.x];
    __syncthreads();

    int wid = threadIdx.x >> 5, lane = threadIdx.x & 31;
    for (int row = blockIdx.x * 8 + wid; row < B_ * T_; row += gridDim.x * 8) {
        float h[16];
        const float* hp = &g_hs[(size_t)row * H_ + lane * 16];
#pragma unroll
        for (int i = 0; i < 4; i++) {
            float4 v = *(const float4*)&hp[i * 4];
            h[i * 4 + 0] = v.x; h[i * 4 + 1] = v.y;
            h[i * 4 + 2] = v.z; h[i * 4 + 3] = v.w;
        }
#pragma unroll
        for (int o = 0; o < 10; o++) {
            float p = 0.f;
#pragma unroll
            for (int i = 0; i < 16; i++) p += h[i] * sw[(lane * 16 + i) * 10 + o];
            p += __shfl_xor_sync(0xffffffff, p, 16);
            p += __shfl_xor_sync(0xffffffff, p, 8);
            p += __shfl_xor_sync(0xffffffff, p, 4);
            p += __shfl_xor_sync(0xffffffff, p, 2);
            p += __shfl_xor_sync(0xffffffff, p, 1);
            if (lane == 0) out[row * 10 + o] = p + sb[o];
        }
    }
}

// ---------------- launch -----------------------------------------------------
extern "C" void kernel_launch(void* const* d_in, const int* in_sizes, int n_in,
                              void* d_out, int out_size) {
    const float* x      = (const float*)d_in[0];
    const float* W_in   = (const float*)d_in[1];
    const float* b_in   = (const float*)d_in[2];
    const float* W_rec  = (const float*)d_in[3];
    const float* bias   = (const float*)d_in[4];
    const float* W_tau1 = (const float*)d_in[5];
    const float* b_tau1 = (const float*)d_in[6];
    const float* W_tau2 = (const float*)d_in[7];
    const float* b_tau2 = (const float*)d_in[8];
    const float* W_out  = (const float*)d_in[9];
    const float* b_out  = (const float*)d_in[10];
    float* out = (float*)d_out;

    float* d_xp; cudaGetSymbolAddress((void**)&d_xp, g_xp);
    float* d_xq; cudaGetSymbolAddress((void**)&d_xq, g_xq);
    float* d_weff; cudaGetSymbolAddress((void**)&d_weff, g_weff);
    float* d_beff; cudaGetSymbolAddress((void**)&d_beff, g_beff);

    cudaFuncSetAttribute(proj_gemm<H_>, cudaFuncAttributeMaxDynamicSharedMemorySize, XP_SMEM);
    cudaFuncSetAttribute(proj_gemm<256>, cudaFuncAttributeMaxDynamicSharedMemorySize, XP_SMEM);
    cudaFuncSetAttribute(scan_kernel, cudaFuncAttributeMaxDynamicSharedMemorySize, SCAN_SMEM);
    cudaFuncSetAttribute(scan_kernel, cudaFuncAttributeNonPortableClusterSizeAllowed, 1);

    weff_gemm<<<dim3(4, 2), 256>>>(W_in, W_tau1);
    beff_kernel<<<256, 64>>>(b_in, W_tau1, b_tau1);
    proj_gemm<H_><<<dim3(8, 1024), 256, XP_SMEM>>>(x, W_in, b_in, d_xp);
    proj_gemm<256><<<dim3(4, 1024), 256, XP_SMEM>>>(x, d_weff, d_beff, d_xq);
    scan_kernel<<<GRID_SCAN, NT, SCAN_SMEM>>>(W_rec, bias, W_tau1, b_tau1,
                                              W_tau2, b_tau2);
    out_gemm<<<2048, 256>>>(W_out, b_out, out);
}

// round 15
// speedup vs baseline: 1.1733x; 1.1733x over previous
#include <cuda_runtime.h>
#include <math.h>

#define B_ 64
#define T_ 1024
#define I_ 128
#define H_ 512

#define CLUSTER 16
#define GRID_SCAN 128
#define NT 256

// ---------------- device scratch (no allocations allowed) -------------------
__device__ float g_xp[B_ * T_ * H_];        // x @ W_in + b_in        [B,T,512]
__device__ float g_xq[B_ * T_ * (H_ / 2)];  // x @ W_eff + b_eff      [B,T,256]
__device__ float g_hs[B_ * T_ * H_];        // all hidden states      [B,T,512]
__device__ float g_weff[I_ * (H_ / 2)];     // W_in @ W_tau1[:512]    [128,256]
__device__ float g_beff[H_ / 2];            // b_in @ W1x + b_tau1    [256]

// ---------------- scan SMEM layout (floats) ---------------------------------
#define H_S   516
#define W1_S  516
#define WR_S  516
#define W2_S  260
#define Z1_S  260
#define S1_S  129     // A1 partial stride (odd -> conflict-free scalar access)
#define S2_S  260     // A2/B1 partial stride (float4-aligned, odd 16B units)
#define HBUF  (8 * H_S)                       // 4128 floats per h buffer
constexpr int P_H0   = 0;                     // [8][516]  h buffer 0
constexpr int P_H1   = HBUF;                  // [8][516]  h buffer 1
constexpr int P_WT1  = 2 * HBUF;              // [16][516] W_tau1 h-part ^T
constexpr int P_WREC = P_WT1 + 16 * W1_S;     // [32][516] W_rec rows
constexpr int P_WT2  = P_WREC + 32 * WR_S;    // [32][260] W_tau2 ^T
constexpr int P_Z1   = P_WT2 + 32 * W2_S;     // [8][260]  full z1 (DSMEM-filled)
constexpr int P_SCR  = P_Z1 + 8 * Z1_S;       // [8320]    shared partials
constexpr int P_B1   = P_SCR + 8320;          // [16]
constexpr int P_BIAS = P_B1 + 16;             // [32]
constexpr int P_B2   = P_BIAS + 32;           // [32]
constexpr int P_MBAR = P_B2 + 32;             // [4] two 8B mbarriers (8B aligned)
constexpr int SCAN_FLOATS = P_MBAR + 4;
constexpr int SCAN_SMEM = SCAN_FLOATS * 4;    // ~207 KB

constexpr int XP_SMEM = (64 * 132 + 128 * 68) * 4;  // ~68.6 KB

// ---------------- helpers ----------------------------------------------------
__device__ __forceinline__ void fma2(unsigned long long& d,
                                     unsigned long long a,
                                     unsigned long long b) {
    asm("fma.rn.f32x2 %0, %1, %2, %0;" : "+l"(d) : "l"(a), "l"(b));
}
__device__ __forceinline__ float pair_sum(unsigned long long v) {
    return __uint_as_float((unsigned)v) + __uint_as_float((unsigned)(v >> 32));
}
__device__ __forceinline__ void st_cluster(unsigned addr, unsigned rank, float v) {
    unsigned ra;
    asm volatile("mapa.shared::cluster.u32 %0, %1, %2;" : "=r"(ra) : "r"(addr), "r"(rank));
    asm volatile("st.shared::cluster.f32 [%0], %1;" :: "r"(ra), "f"(v) : "memory");
}
// Remote mbarrier arrive (release, cluster scope via shared::cluster space).
__device__ __forceinline__ void mbar_arrive_cluster(unsigned addr, unsigned rank) {
    unsigned ra;
    asm volatile("mapa.shared::cluster.u32 %0, %1, %2;" : "=r"(ra) : "r"(addr), "r"(rank));
    asm volatile("mbarrier.arrive.shared::cluster.b64 _, [%0];" :: "r"(ra) : "memory");
}
// Local mbarrier wait with cluster-scope acquire (orders peers' DSMEM stores).
__device__ __forceinline__ void mbar_wait_parity(unsigned addr, unsigned parity) {
    asm volatile(
        "{\n\t"
        ".reg .pred P;\n\t"
        "MWAIT_%=:\n\t"
        "mbarrier.try_wait.parity.acquire.cluster.shared::cta.b64 P, [%0], %1, 0x989680;\n\t"
        "@P bra.uni MDONE_%=;\n\t"
        "bra.uni MWAIT_%=;\n\t"
        "MDONE_%=:\n\t"
        "}"
        :: "r"(addr), "r"(parity) : "memory");
}
#define CL_ARRIVE() asm volatile("barrier.cluster.arrive.aligned;" ::: "memory")
#define CL_WAIT()   asm volatile("barrier.cluster.wait.aligned;"   ::: "memory")
#define CLUSTER_SYNC() do { CL_ARRIVE(); CL_WAIT(); } while (0)

// ---------------- W_eff = W_in @ W_tau1[:512,:] ------------------------------
__global__ void __launch_bounds__(256) weff_gemm(const float* __restrict__ Win,
                                                 const float* __restrict__ Wt1) {
    __shared__ float sa[64 * 68];
    __shared__ float sb[64 * 68];
    const int tid = threadIdx.x;
    const int n0 = blockIdx.x * 64, m0 = blockIdx.y * 64;
    const int ty = tid >> 4, tx = tid & 15;
    float acc[4][4];
#pragma unroll
    for (int i = 0; i < 4; i++)
#pragma unroll
        for (int j = 0; j < 4; j++) acc[i][j] = 0.f;

    for (int kt = 0; kt < 512; kt += 64) {
        for (int f = tid; f < 64 * 16; f += 256) {
            int r = f >> 4, q = (f & 15) << 2;
            *(float4*)&sa[r * 68 + q] = *(const float4*)&Win[(size_t)(m0 + r) * 512 + kt + q];
            *(float4*)&sb[r * 68 + q] = *(const float4*)&Wt1[(size_t)(kt + r) * 256 + n0 + q];
        }
        __syncthreads();
#pragma unroll 8
        for (int k = 0; k < 64; k++) {
            float a[4];
#pragma unroll
            for (int i = 0; i < 4; i++) a[i] = sa[(ty * 4 + i) * 68 + k];
            float4 w = *(const float4*)&sb[k * 68 + tx * 4];
#pragma unroll
            for (int i = 0; i < 4; i++) {
                acc[i][0] += a[i] * w.x; acc[i][1] += a[i] * w.y;
                acc[i][2] += a[i] * w.z; acc[i][3] += a[i] * w.w;
            }
        }
        __syncthreads();
    }
#pragma unroll
    for (int i = 0; i < 4; i++) {
        float4 r;
        r.x = acc[i][0]; r.y = acc[i][1]; r.z = acc[i][2]; r.w = acc[i][3];
        *(float4*)&g_weff[(size_t)(m0 + ty * 4 + i) * 256 + n0 + tx * 4] = r;
    }
}

// ---------------- b_eff = b_in @ W1x + b_tau1 --------------------------------
__global__ void __launch_bounds__(64) beff_kernel(const float* __restrict__ b_in,
                                                  const float* __restrict__ Wt1,
                                                  const float* __restrict__ b_tau1) {
    __shared__ float red[64];
    const int c = blockIdx.x, lane = threadIdx.x;
    float p = 0.f;
    for (int k = lane; k < 512; k += 64) p += b_in[k] * Wt1[(size_t)k * 256 + c];
    red[lane] = p;
    __syncthreads();
    if (lane < 32) {
        float v = red[lane] + red[lane + 32];
        v += __shfl_xor_sync(0xffffffff, v, 16);
        v += __shfl_xor_sync(0xffffffff, v, 8);
        v += __shfl_xor_sync(0xffffffff, v, 4);
        v += __shfl_xor_sync(0xffffffff, v, 2);
        v += __shfl_xor_sync(0xffffffff, v, 1);
        if (lane == 0) g_beff[c] = v + b_tau1[c];
    }
}

// ---------------- generic projection: out = x @ W + b -----------------------
template <int NCOLS>
__global__ void __launch_bounds__(256) proj_gemm(const float* __restrict__ x,
                                                 const float* __restrict__ W,
                                                 const float* __restrict__ bvec,
                                                 float* __restrict__ outp) {
    extern __shared__ float sm[];
    float* sx = sm;                 // [64][132]
    float* sw = sm + 64 * 132;      // [128][68]
    const int tid = threadIdx.x;
    const int n0 = blockIdx.x * 64;
    const int r0 = blockIdx.y * 64;

    for (int f = tid; f < 64 * 32; f += 256) {
        int row = f >> 5, kq = (f & 31) << 2;
        *(float4*)(sx + row * 132 + kq) =
            *(const float4*)(x + (size_t)(r0 + row) * I_ + kq);
    }
    for (int f = tid; f < 128 * 16; f += 256) {
        int k = f >> 4, nq = (f & 15) << 2;
        *(float4*)(sw + k * 68 + nq) =
            *(const float4*)(W + (size_t)k * NCOLS + n0 + nq);
    }
    __syncthreads();

    const int ty = tid >> 4, tx = tid & 15;
    float acc[4][4];
#pragma unroll
    for (int i = 0; i < 4; i++)
#pragma unroll
        for (int j = 0; j < 4; j++) acc[i][j] = 0.f;

#pragma unroll 8
    for (int k = 0; k < 128; k++) {
        float a[4];
#pragma unroll
        for (int i = 0; i < 4; i++) a[i] = sx[(ty * 4 + i) * 132 + k];
        float4 w = *(const float4*)(sw + k * 68 + tx * 4);
#pragma unroll
        for (int i = 0; i < 4; i++) {
            acc[i][0] += a[i] * w.x; acc[i][1] += a[i] * w.y;
            acc[i][2] += a[i] * w.z; acc[i][3] += a[i] * w.w;
        }
    }

    float4 bv = *(const float4*)(bvec + n0 + tx * 4);
#pragma unroll
    for (int i = 0; i < 4; i++) {
        float4 r;
        r.x = acc[i][0] + bv.x; r.y = acc[i][1] + bv.y;
        r.z = acc[i][2] + bv.z; r.w = acc[i][3] + bv.w;
        *(float4*)(outp + (size_t)(r0 + ty * 4 + i) * NCOLS + n0 + tx * 4) = r;
    }
}

// ---------------- persistent clustered scan ----------------------------------
__global__ void __launch_bounds__(NT, 1) __cluster_dims__(CLUSTER, 1, 1)
scan_kernel(const float* __restrict__ W_rec, const float* __restrict__ bias,
            const float* __restrict__ W_tau1, const float* __restrict__ b_tau1,
            const float* __restrict__ W_tau2, const float* __restrict__ b_tau2) {
    extern __shared__ float sm[];
    const int tid = threadIdx.x;
    const int cid = blockIdx.x & (CLUSTER - 1);
    const int bg  = blockIdx.x >> 4;
    const int r0  = bg * 8;
    const int hc0 = cid * 32;
    const int zc0 = cid * 16;
    const unsigned sbase = (unsigned)__cvta_generic_to_shared(sm);
    const unsigned mbar_z1 = sbase + (unsigned)P_MBAR * 4u;
    const unsigned mbar_h  = sbase + (unsigned)P_MBAR * 4u + 8u;

    // ---- one-time weight staging ----
    for (int e = tid; e < 16 * 512; e += NT) {     // W_tau1 h-part, transposed
        int c = e >> 9, k = e & 511;
        sm[P_WT1 + c * W1_S + k] = __ldg(&W_tau1[(size_t)(512 + k) * 256 + zc0 + c]);
    }
    for (int e = tid; e < 32 * 512; e += NT) {     // W_rec rows
        int c = e >> 9, k = e & 511;
        sm[P_WREC + c * WR_S + k] = __ldg(&W_rec[(size_t)(hc0 + c) * 512 + k]);
    }
    for (int e = tid; e < 32 * 256; e += NT) {     // W_tau2 transposed
        int c = e >> 8, k = e & 255;
        sm[P_WT2 + c * W2_S + k] = __ldg(&W_tau2[(size_t)k * 512 + hc0 + c]);
    }
    if (tid < 16) sm[P_B1 + tid]   = b_tau1[zc0 + tid];
    if (tid < 32) sm[P_BIAS + tid] = bias[hc0 + tid];
    if (tid < 32) sm[P_B2 + tid]   = b_tau2[hc0 + tid];
    // zero both h buffers
    for (int e = tid; e < 2 * HBUF; e += NT) sm[e] = 0.f;
    if (tid == 0) {
        asm volatile("mbarrier.init.shared.b64 [%0], %1;" :: "r"(mbar_z1), "r"(128 * CLUSTER) : "memory");
        asm volatile("mbarrier.init.shared.b64 [%0], %1;" :: "r"(mbar_h),  "r"(256 * CLUSTER) : "memory");
    }
    __syncthreads();

    // ---- register-resident weights ----
    const int sA = tid & 31;
    const int tcA = (tid >> 5) * 4;
    unsigned long long wrec[4][4][2];   // A2: k = sA*4 + j*128, j<4
#pragma unroll
    for (int j = 0; j < 4; j++)
#pragma unroll
        for (int c = 0; c < 4; c++) {
            double2 wv = *(const double2*)&sm[P_WREC + (tcA + c) * WR_S + sA * 4 + j * 128];
            wrec[j][c][0] = __double_as_longlong(wv.x);
            wrec[j][c][1] = __double_as_longlong(wv.y);
        }
    unsigned long long wt2[2][4][2];    // B1: k = sA*4 + j*128, j<2
#pragma unroll
    for (int j = 0; j < 2; j++)
#pragma unroll
        for (int c = 0; c < 4; c++) {
            double2 wv = *(const double2*)&sm[P_WT2 + (tcA + c) * W2_S + sA * 4 + j * 128];
            wt2[j][c][0] = __double_as_longlong(wv.x);
            wt2[j][c][1] = __double_as_longlong(wv.y);
        }
    const int sZ = tid & 63;
    const int tcZ = (tid >> 6) * 4;
    unsigned long long wt1[2][4][2];    // A1: k = sZ*4 + j*256, j<2
#pragma unroll
    for (int j = 0; j < 2; j++)
#pragma unroll
        for (int c = 0; c < 4; c++) {
            double2 wv = *(const double2*)&sm[P_WT1 + (tcZ + c) * W1_S + sZ * 4 + j * 256];
            wt1[j][c][0] = __double_as_longlong(wv.x);
            wt1[j][c][1] = __double_as_longlong(wv.y);
        }

    CLUSTER_SYNC();   // mbarriers + weights visible cluster-wide

    const int rr = tid >> 5;      // 0..7 (h mapping)
    const int cc = tid & 31;      // 0..31
    const int zr = tid >> 4;      // z1 mapping (tid<128)
    const int zc = tid & 15;

    float xv  = __ldcg(&g_xp[((size_t)(r0 + rr) * T_) * H_ + hc0 + cc]);
    float xqv = 0.f;
    if (tid < 128)
        xqv = __ldcg(&g_xq[((size_t)(r0 + zr) * T_) * 256 + zc0 + zc]);

    float drv = 0.f;

    for (int t = 0; t < T_; t++) {
        const int pcur  = (t & 1) ? P_H1 : P_H0;
        const int pnext = (t & 1) ? P_H0 : P_H1;
        const unsigned parity = (unsigned)(t & 1);

        // ---- A1: z1 partials (8r x 16c, k=512), reg-W, 8r x 4c, S=64 ----
        {
            const float* ap = &sm[pcur];
            unsigned long long acc[32];
#pragma unroll
            for (int e = 0; e < 32; e++) acc[e] = 0ull;
#pragma unroll
            for (int j = 0; j < 2; j++) {
                const int k = sZ * 4 + j * 256;
#pragma unroll
                for (int i = 0; i < 8; i++) {
                    double2 av = *(const double2*)&ap[i * H_S + k];
                    unsigned long long a0 = __double_as_longlong(av.x);
                    unsigned long long a1 = __double_as_longlong(av.y);
#pragma unroll
                    for (int c = 0; c < 4; c++) {
                        fma2(acc[i * 4 + c], a0, wt1[j][c][0]);
                        fma2(acc[i * 4 + c], a1, wt1[j][c][1]);
                    }
                }
            }
#pragma unroll
            for (int i = 0; i < 8; i++)
#pragma unroll
                for (int c = 0; c < 4; c++)
                    sm[P_SCR + sZ * S1_S + i * 16 + tcZ + c] = pair_sum(acc[i * 4 + c]);
        }
        __syncthreads();

        // ---- z1 reduce + relu + DSMEM push + remote arrives ----
        if (tid < 128) {
            float a0 = 0.f, a1 = 0.f;
#pragma unroll
            for (int s = 0; s < 64; s += 2) {
                a0 += sm[P_SCR + (s + 0) * S1_S + zr * 16 + zc];
                a1 += sm[P_SCR + (s + 1) * S1_S + zr * 16 + zc];
            }
            float z = sm[P_B1 + zc] + xqv + (a0 + a1);
            z = fmaxf(z, 0.f);
            unsigned a = sbase + (unsigned)(P_Z1 + zr * Z1_S + zc0 + zc) * 4u;
#pragma unroll
            for (unsigned rk = 0; rk < CLUSTER; rk++) st_cluster(a, rk, z);
#pragma unroll
            for (unsigned rk = 0; rk < CLUSTER; rk++) mbar_arrive_cluster(mbar_z1, rk);
        }
        __syncthreads();                   // protect P_SCR (A2 writes next)

        // ---- A2: drive partials (8r x 32c, k=512), reg-W, 8r x 4c, S=32 ----
        {
            const float* ap = &sm[pcur];
            unsigned long long acc[32];
#pragma unroll
            for (int e = 0; e < 32; e++) acc[e] = 0ull;
#pragma unroll
            for (int j = 0; j < 4; j++) {
                const int k = sA * 4 + j * 128;
#pragma unroll
                for (int i = 0; i < 8; i++) {
                    double2 av = *(const double2*)&ap[i * H_S + k];
                    unsigned long long a0 = __double_as_longlong(av.x);
                    unsigned long long a1 = __double_as_longlong(av.y);
#pragma unroll
                    for (int c = 0; c < 4; c++) {
                        fma2(acc[i * 4 + c], a0, wrec[j][c][0]);
                        fma2(acc[i * 4 + c], a1, wrec[j][c][1]);
                    }
                }
            }
#pragma unroll
            for (int i = 0; i < 8; i++) {
                float4 v;
                v.x = pair_sum(acc[i * 4 + 0]);
                v.y = pair_sum(acc[i * 4 + 1]);
                v.z = pair_sum(acc[i * 4 + 2]);
                v.w = pair_sum(acc[i * 4 + 3]);
                *(float4*)&sm[P_SCR + sA * S2_S + i * 32 + tcA] = v;
            }
        }
        __syncthreads();

        // ---- drive reduce (32 partials) -> tanh ----
        {
            float pre = xv + sm[P_BIAS + cc];
#pragma unroll
            for (int s = 0; s < 32; s++) pre += sm[P_SCR + s * S2_S + tid];
            float e2 = __expf(2.f * pre);
            drv = 1.f - 2.f / (e2 + 1.f);
        }
        mbar_wait_parity(mbar_z1, parity); // z1 resident in local P_Z1
        __syncthreads();                   // protect P_SCR reuse

        // ---- B1: tau partials (8r x 32c, k=256), reg-W, 8r x 4c, S=32 ----
        {
            const float* ap = &sm[P_Z1];
            unsigned long long acc[32];
#pragma unroll
            for (int e = 0; e < 32; e++) acc[e] = 0ull;
#pragma unroll
            for (int j = 0; j < 2; j++) {
                const int k = sA * 4 + j * 128;
#pragma unroll
                for (int i = 0; i < 8; i++) {
                    double2 av = *(const double2*)&ap[i * Z1_S + k];
                    unsigned long long a0 = __double_as_longlong(av.x);
                    unsigned long long a1 = __double_as_longlong(av.y);
#pragma unroll
                    for (int c = 0; c < 4; c++) {
                        fma2(acc[i * 4 + c], a0, wt2[j][c][0]);
                        fma2(acc[i * 4 + c], a1, wt2[j][c][1]);
                    }
                }
            }
#pragma unroll
            for (int i = 0; i < 8; i++) {
                float4 v;
                v.x = pair_sum(acc[i * 4 + 0]);
                v.y = pair_sum(acc[i * 4 + 1]);
                v.z = pair_sum(acc[i * 4 + 2]);
                v.w = pair_sum(acc[i * 4 + 3]);
                *(float4*)&sm[P_SCR + sA * S2_S + i * 32 + tcA] = v;
            }
        }
        __syncthreads();

        // ---- B2: tau reduce + Euler + DSMEM h push + remote arrives ----
        {
            float sv = sm[P_B2 + cc];
#pragma unroll
            for (int s = 0; s < 32; s++) sv += sm[P_SCR + s * S2_S + tid];
            float sig = 1.f / (1.f + __expf(-sv));
            float tau = 5.f + sig * 45.f;
            float hold = sm[pcur + rr * H_S + hc0 + cc];
            float hnew = hold + (drv - hold) / tau;
            unsigned a = sbase + (unsigned)(pnext + rr * H_S + hc0 + cc) * 4u;
#pragma unroll
            for (unsigned rk = 0; rk < CLUSTER; rk++) st_cluster(a, rk, hnew);
#pragma unroll
            for (unsigned rk = 0; rk < CLUSTER; rk++) mbar_arrive_cluster(mbar_h, rk);
            __stcg(&g_hs[((size_t)(r0 + rr) * T_ + t) * H_ + hc0 + cc], hnew);
        }
        __syncthreads();                   // protect P_SCR (next A1 writes)
        {
            int tn = (t + 1 < T_) ? t + 1 : t;          // prefetch next step
            xv = __ldcg(&g_xp[((size_t)(r0 + rr) * T_ + tn) * H_ + hc0 + cc]);
            if (tid < 128)
                xqv = __ldcg(&g_xq[((size_t)(r0 + zr) * T_ + tn) * 256 + zc0 + zc]);
        }
        mbar_wait_parity(mbar_h, parity);  // h(t+1) resident in pnext
    }

    CLUSTER_SYNC();   // keep CTAs alive until all remote traffic landed
}

// ---------------- out = hs @ W_out + b_out ----------------------------------
__global__ void __launch_bounds__(256) out_gemm(const float* __restrict__ W_out,
                                                const float* __restrict__ b_out,
                                                float* __restrict__ out) {
    __shared__ float sw[H_ * 10];
    __shared__ float sb[10];
    for (int e = threadIdx.x; e < H_ * 10; e += 256) sw[e] = W_out[e];
    if (threadIdx.x < 10) sb[threadIdx.x] = b_out[threadIdx.x];
    __syncthreads();

    int wid = threadIdx.x >> 5, lane = threadIdx.x & 31;
    for (int row = blockIdx.x * 8 + wid; row < B_ * T_; row += gridDim.x * 8) {
        float h[16];
        const float* hp = &g_hs[(size_t)row * H_ + lane * 16];
#pragma unroll
        for (int i = 0; i < 4; i++) {
            float4 v = *(const float4*)&hp[i * 4];
            h[i * 4 + 0] = v.x; h[i * 4 + 1] = v.y;
            h[i * 4 + 2] = v.z; h[i * 4 + 3] = v.w;
        }
#pragma unroll
        for (int o = 0; o < 10; o++) {
            float p = 0.f;
#pragma unroll
            for (int i = 0; i < 16; i++) p += h[i] * sw[(lane * 16 + i) * 10 + o];
            p += __shfl_xor_sync(0xffffffff, p, 16);
            p += __shfl_xor_sync(0xffffffff, p, 8);
            p += __shfl_xor_sync(0xffffffff, p, 4);
            p += __shfl_xor_sync(0xffffffff, p, 2);
            p += __shfl_xor_sync(0xffffffff, p, 1);
            if (lane == 0) out[row * 10 + o] = p + sb[o];
        }
    }
}

// ---------------- launch -----------------------------------------------------
extern "C" void kernel_launch(void* const* d_in, const int* in_sizes, int n_in,
                              void* d_out, int out_size) {
    const float* x      = (const float*)d_in[0];
    const float* W_in   = (const float*)d_in[1];
    const float* b_in   = (const float*)d_in[2];
    const float* W_rec  = (const float*)d_in[3];
    const float* bias   = (const float*)d_in[4];
    const float* W_tau1 = (const float*)d_in[5];
    const float* b_tau1 = (const float*)d_in[6];
    const float* W_tau2 = (const float*)d_in[7];
    const float* b_tau2 = (const float*)d_in[8];
    const float* W_out  = (const float*)d_in[9];
    const float* b_out  = (const float*)d_in[10];
    float* out = (float*)d_out;

    float* d_xp; cudaGetSymbolAddress((void**)&d_xp, g_xp);
    float* d_xq; cudaGetSymbolAddress((void**)&d_xq, g_xq);
    float* d_weff; cudaGetSymbolAddress((void**)&d_weff, g_weff);
    float* d_beff; cudaGetSymbolAddress((void**)&d_beff, g_beff);

    cudaFuncSetAttribute(proj_gemm<H_>, cudaFuncAttributeMaxDynamicSharedMemorySize, XP_SMEM);
    cudaFuncSetAttribute(proj_gemm<256>, cudaFuncAttributeMaxDynamicSharedMemorySize, XP_SMEM);
    cudaFuncSetAttribute(scan_kernel, cudaFuncAttributeMaxDynamicSharedMemorySize, SCAN_SMEM);
    cudaFuncSetAttribute(scan_kernel, cudaFuncAttributeNonPortableClusterSizeAllowed, 1);

    weff_gemm<<<dim3(4, 2), 256>>>(W_in, W_tau1);
    beff_kernel<<<256, 64>>>(b_in, W_tau1, b_tau1);
    proj_gemm<H_><<<dim3(8, 1024), 256, XP_SMEM>>>(x, W_in, b_in, d_xp);
    proj_gemm<256><<<dim3(4, 1024), 256, XP_SMEM>>>(x, d_weff, d_beff, d_xq);
    scan_kernel<<<GRID_SCAN, NT, SCAN_SMEM>>>(W_rec, bias, W_tau1, b_tau1,
                                              W_tau2, b_tau2);
    out_gemm<<<2048, 256>>>(W_out, b_out, out);
}

// round 16
// speedup vs baseline: 1.1779x; 1.0040x over previous
#include <cuda_runtime.h>
#include <math.h>

#define B_ 64
#define T_ 1024
#define I_ 128
#define H_ 512

#define CLUSTER 16
#define GRID_SCAN 128
#define NT 256

// ---------------- device scratch (no allocations allowed) -------------------
__device__ float g_xp[B_ * T_ * H_];        // x @ W_in + b_in        [B,T,512]
__device__ float g_xq[B_ * T_ * (H_ / 2)];  // x @ W_eff + b_eff      [B,T,256]
__device__ float g_hs[B_ * T_ * H_];        // all hidden states      [B,T,512]
__device__ float g_weff[I_ * (H_ / 2)];     // W_in @ W_tau1[:512]    [128,256]
__device__ float g_beff[H_ / 2];            // b_in @ W1x + b_tau1    [256]

// ---------------- scan SMEM layout (floats) ---------------------------------
#define H_S   516
#define W1_S  516
#define WR_S  516
#define W2_S  260
#define Z1_S  260
#define S1_S  129     // A1 partial stride (odd -> conflict-free scalar access)
#define S2_S  260     // A2/B1 partial stride (float4-aligned, odd 16B units)
#define HBUF  (8 * H_S)                       // 4128 floats per h buffer
constexpr int P_H0   = 0;                     // [8][516]  h buffer 0
constexpr int P_H1   = HBUF;                  // [8][516]  h buffer 1
constexpr int P_WT1  = 2 * HBUF;              // [16][516] W_tau1 ^T staging -> SCRA
constexpr int P_WREC = P_WT1 + 16 * W1_S;     // [32][516] W_rec staging   -> SCRB
constexpr int P_WT2  = P_WREC + 32 * WR_S;    // [32][260] W_tau2 ^T staging-> SCRC
constexpr int P_Z1   = P_WT2 + 32 * W2_S;     // [8][260]  full z1 (DSMEM-filled)
// scratch aliases over the (post-prologue dead) weight-staging regions:
constexpr int P_SCRA = P_WT1;                 // A1 partials: 64*129 = 8256 (= 16*516)
constexpr int P_SCRB = P_WREC;                // A2 partials: 32*260 = 8320 (< 16512)
constexpr int P_SCRC = P_WT2;                 // B1 partials: 32*260 = 8320 (= 8320)
constexpr int P_B1   = P_Z1 + 8 * Z1_S;       // [16]
constexpr int P_BIAS = P_B1 + 16;             // [32]
constexpr int P_B2   = P_BIAS + 32;           // [32]
constexpr int P_MBAR = P_B2 + 32;             // [4] two 8B mbarriers (8B aligned)
constexpr int SCAN_FLOATS = P_MBAR + 4;
constexpr int SCAN_SMEM = SCAN_FLOATS * 4;    // ~174 KB

constexpr int XP_SMEM = (64 * 132 + 128 * 68) * 4;  // ~68.6 KB

// ---------------- helpers ----------------------------------------------------
__device__ __forceinline__ void fma2(unsigned long long& d,
                                     unsigned long long a,
                                     unsigned long long b) {
    asm("fma.rn.f32x2 %0, %1, %2, %0;" : "+l"(d) : "l"(a), "l"(b));
}
__device__ __forceinline__ float pair_sum(unsigned long long v) {
    return __uint_as_float((unsigned)v) + __uint_as_float((unsigned)(v >> 32));
}
__device__ __forceinline__ void st_cluster(unsigned addr, unsigned rank, float v) {
    unsigned ra;
    asm volatile("mapa.shared::cluster.u32 %0, %1, %2;" : "=r"(ra) : "r"(addr), "r"(rank));
    asm volatile("st.shared::cluster.f32 [%0], %1;" :: "r"(ra), "f"(v) : "memory");
}
// Remote mbarrier arrive (release, cluster scope via shared::cluster space).
__device__ __forceinline__ void mbar_arrive_cluster(unsigned addr, unsigned rank) {
    unsigned ra;
    asm volatile("mapa.shared::cluster.u32 %0, %1, %2;" : "=r"(ra) : "r"(addr), "r"(rank));
    asm volatile("mbarrier.arrive.shared::cluster.b64 _, [%0];" :: "r"(ra) : "memory");
}
// Local mbarrier wait with cluster-scope acquire (orders peers' DSMEM stores).
__device__ __forceinline__ void mbar_wait_parity(unsigned addr, unsigned parity) {
    asm volatile(
        "{\n\t"
        ".reg .pred P;\n\t"
        "MWAIT_%=:\n\t"
        "mbarrier.try_wait.parity.acquire.cluster.shared::cta.b64 P, [%0], %1, 0x989680;\n\t"
        "@P bra.uni MDONE_%=;\n\t"
        "bra.uni MWAIT_%=;\n\t"
        "MDONE_%=:\n\t"
        "}"
        :: "r"(addr), "r"(parity) : "memory");
}
#define CL_ARRIVE() asm volatile("barrier.cluster.arrive.aligned;" ::: "memory")
#define CL_WAIT()   asm volatile("barrier.cluster.wait.aligned;"   ::: "memory")
#define CLUSTER_SYNC() do { CL_ARRIVE(); CL_WAIT(); } while (0)

// ---------------- W_eff = W_in @ W_tau1[:512,:] ------------------------------
__global__ void __launch_bounds__(256) weff_gemm(const float* __restrict__ Win,
                                                 const float* __restrict__ Wt1) {
    __shared__ float sa[64 * 68];
    __shared__ float sb[64 * 68];
    const int tid = threadIdx.x;
    const int n0 = blockIdx.x * 64, m0 = blockIdx.y * 64;
    const int ty = tid >> 4, tx = tid & 15;
    float acc[4][4];
#pragma unroll
    for (int i = 0; i < 4; i++)
#pragma unroll
        for (int j = 0; j < 4; j++) acc[i][j] = 0.f;

    for (int kt = 0; kt < 512; kt += 64) {
        for (int f = tid; f < 64 * 16; f += 256) {
            int r = f >> 4, q = (f & 15) << 2;
            *(float4*)&sa[r * 68 + q] = *(const float4*)&Win[(size_t)(m0 + r) * 512 + kt + q];
            *(float4*)&sb[r * 68 + q] = *(const float4*)&Wt1[(size_t)(kt + r) * 256 + n0 + q];
        }
        __syncthreads();
#pragma unroll 8
        for (int k = 0; k < 64; k++) {
            float a[4];
#pragma unroll
            for (int i = 0; i < 4; i++) a[i] = sa[(ty * 4 + i) * 68 + k];
            float4 w = *(const float4*)&sb[k * 68 + tx * 4];
#pragma unroll
            for (int i = 0; i < 4; i++) {
                acc[i][0] += a[i] * w.x; acc[i][1] += a[i] * w.y;
                acc[i][2] += a[i] * w.z; acc[i][3] += a[i] * w.w;
            }
        }
        __syncthreads();
    }
#pragma unroll
    for (int i = 0; i < 4; i++) {
        float4 r;
        r.x = acc[i][0]; r.y = acc[i][1]; r.z = acc[i][2]; r.w = acc[i][3];
        *(float4*)&g_weff[(size_t)(m0 + ty * 4 + i) * 256 + n0 + tx * 4] = r;
    }
}

// ---------------- b_eff = b_in @ W1x + b_tau1 --------------------------------
__global__ void __launch_bounds__(64) beff_kernel(const float* __restrict__ b_in,
                                                  const float* __restrict__ Wt1,
                                                  const float* __restrict__ b_tau1) {
    __shared__ float red[64];
    const int c = blockIdx.x, lane = threadIdx.x;
    float p = 0.f;
    for (int k = lane; k < 512; k += 64) p += b_in[k] * Wt1[(size_t)k * 256 + c];
    red[lane] = p;
    __syncthreads();
    if (lane < 32) {
        float v = red[lane] + red[lane + 32];
        v += __shfl_xor_sync(0xffffffff, v, 16);
        v += __shfl_xor_sync(0xffffffff, v, 8);
        v += __shfl_xor_sync(0xffffffff, v, 4);
        v += __shfl_xor_sync(0xffffffff, v, 2);
        v += __shfl_xor_sync(0xffffffff, v, 1);
        if (lane == 0) g_beff[c] = v + b_tau1[c];
    }
}

// ---------------- generic projection: out = x @ W + b -----------------------
template <int NCOLS>
__global__ void __launch_bounds__(256) proj_gemm(const float* __restrict__ x,
                                                 const float* __restrict__ W,
                                                 const float* __restrict__ bvec,
                                                 float* __restrict__ outp) {
    extern __shared__ float sm[];
    float* sx = sm;                 // [64][132]
    float* sw = sm + 64 * 132;      // [128][68]
    const int tid = threadIdx.x;
    const int n0 = blockIdx.x * 64;
    const int r0 = blockIdx.y * 64;

    for (int f = tid; f < 64 * 32; f += 256) {
        int row = f >> 5, kq = (f & 31) << 2;
        *(float4*)(sx + row * 132 + kq) =
            *(const float4*)(x + (size_t)(r0 + row) * I_ + kq);
    }
    for (int f = tid; f < 128 * 16; f += 256) {
        int k = f >> 4, nq = (f & 15) << 2;
        *(float4*)(sw + k * 68 + nq) =
            *(const float4*)(W + (size_t)k * NCOLS + n0 + nq);
    }
    __syncthreads();

    const int ty = tid >> 4, tx = tid & 15;
    float acc[4][4];
#pragma unroll
    for (int i = 0; i < 4; i++)
#pragma unroll
        for (int j = 0; j < 4; j++) acc[i][j] = 0.f;

#pragma unroll 8
    for (int k = 0; k < 128; k++) {
        float a[4];
#pragma unroll
        for (int i = 0; i < 4; i++) a[i] = sx[(ty * 4 + i) * 132 + k];
        float4 w = *(const float4*)(sw + k * 68 + tx * 4);
#pragma unroll
        for (int i = 0; i < 4; i++) {
            acc[i][0] += a[i] * w.x; acc[i][1] += a[i] * w.y;
            acc[i][2] += a[i] * w.z; acc[i][3] += a[i] * w.w;
        }
    }

    float4 bv = *(const float4*)(bvec + n0 + tx * 4);
#pragma unroll
    for (int i = 0; i < 4; i++) {
        float4 r;
        r.x = acc[i][0] + bv.x; r.y = acc[i][1] + bv.y;
        r.z = acc[i][2] + bv.z; r.w = acc[i][3] + bv.w;
        *(float4*)(outp + (size_t)(r0 + ty * 4 + i) * NCOLS + n0 + tx * 4) = r;
    }
}

// ---------------- persistent clustered scan ----------------------------------
__global__ void __launch_bounds__(NT, 1) __cluster_dims__(CLUSTER, 1, 1)
scan_kernel(const float* __restrict__ W_rec, const float* __restrict__ bias,
            const float* __restrict__ W_tau1, const float* __restrict__ b_tau1,
            const float* __restrict__ W_tau2, const float* __restrict__ b_tau2) {
    extern __shared__ float sm[];
    const int tid = threadIdx.x;
    const int cid = blockIdx.x & (CLUSTER - 1);
    const int bg  = blockIdx.x >> 4;
    const int r0  = bg * 8;
    const int hc0 = cid * 32;
    const int zc0 = cid * 16;
    const unsigned sbase = (unsigned)__cvta_generic_to_shared(sm);
    const unsigned mbar_z1 = sbase + (unsigned)P_MBAR * 4u;
    const unsigned mbar_h  = sbase + (unsigned)P_MBAR * 4u + 8u;

    // ---- one-time weight staging (regions become scratch afterwards) ----
    for (int e = tid; e < 16 * 512; e += NT) {     // W_tau1 h-part, transposed
        int c = e >> 9, k = e & 511;
        sm[P_WT1 + c * W1_S + k] = __ldg(&W_tau1[(size_t)(512 + k) * 256 + zc0 + c]);
    }
    for (int e = tid; e < 32 * 512; e += NT) {     // W_rec rows
        int c = e >> 9, k = e & 511;
        sm[P_WREC + c * WR_S + k] = __ldg(&W_rec[(size_t)(hc0 + c) * 512 + k]);
    }
    for (int e = tid; e < 32 * 256; e += NT) {     // W_tau2 transposed
        int c = e >> 8, k = e & 255;
        sm[P_WT2 + c * W2_S + k] = __ldg(&W_tau2[(size_t)k * 512 + hc0 + c]);
    }
    if (tid < 16) sm[P_B1 + tid]   = b_tau1[zc0 + tid];
    if (tid < 32) sm[P_BIAS + tid] = bias[hc0 + tid];
    if (tid < 32) sm[P_B2 + tid]   = b_tau2[hc0 + tid];
    // zero both h buffers
    for (int e = tid; e < 2 * HBUF; e += NT) sm[e] = 0.f;
    if (tid == 0) {
        asm volatile("mbarrier.init.shared.b64 [%0], %1;" :: "r"(mbar_z1), "r"(128 * CLUSTER) : "memory");
        asm volatile("mbarrier.init.shared.b64 [%0], %1;" :: "r"(mbar_h),  "r"(256 * CLUSTER) : "memory");
    }
    __syncthreads();

    // ---- register-resident weights ----
    const int sA = tid & 31;
    const int tcA = (tid >> 5) * 4;
    unsigned long long wrec[4][4][2];   // A2: k = sA*4 + j*128, j<4
#pragma unroll
    for (int j = 0; j < 4; j++)
#pragma unroll
        for (int c = 0; c < 4; c++) {
            double2 wv = *(const double2*)&sm[P_WREC + (tcA + c) * WR_S + sA * 4 + j * 128];
            wrec[j][c][0] = __double_as_longlong(wv.x);
            wrec[j][c][1] = __double_as_longlong(wv.y);
        }
    unsigned long long wt2[2][4][2];    // B1: k = sA*4 + j*128, j<2
#pragma unroll
    for (int j = 0; j < 2; j++)
#pragma unroll
        for (int c = 0; c < 4; c++) {
            double2 wv = *(const double2*)&sm[P_WT2 + (tcA + c) * W2_S + sA * 4 + j * 128];
            wt2[j][c][0] = __double_as_longlong(wv.x);
            wt2[j][c][1] = __double_as_longlong(wv.y);
        }
    const int sZ = tid & 63;
    const int tcZ = (tid >> 6) * 4;
    unsigned long long wt1[2][4][2];    // A1: k = sZ*4 + j*256, j<2
#pragma unroll
    for (int j = 0; j < 2; j++)
#pragma unroll
        for (int c = 0; c < 4; c++) {
            double2 wv = *(const double2*)&sm[P_WT1 + (tcZ + c) * W1_S + sZ * 4 + j * 256];
            wt1[j][c][0] = __double_as_longlong(wv.x);
            wt1[j][c][1] = __double_as_longlong(wv.y);
        }

    CLUSTER_SYNC();   // regs loaded everywhere; staging regions now free scratch

    const int rr = tid >> 5;      // 0..7 (h mapping)
    const int cc = tid & 31;      // 0..31
    const int zr = tid >> 4;      // z1 mapping (tid<128)
    const int zc = tid & 15;

    float xv  = __ldcg(&g_xp[((size_t)(r0 + rr) * T_) * H_ + hc0 + cc]);
    float xqv = 0.f;
    if (tid < 128)
        xqv = __ldcg(&g_xq[((size_t)(r0 + zr) * T_) * 256 + zc0 + zc]);

    float drv = 0.f;

    for (int t = 0; t < T_; t++) {
        const int pcur  = (t & 1) ? P_H1 : P_H0;
        const int pnext = (t & 1) ? P_H0 : P_H1;
        const unsigned parity = (unsigned)(t & 1);

        // ---- A1: z1 partials (8r x 16c, k=512), reg-W, 8r x 4c, S=64 -> SCRA ----
        {
            const float* ap = &sm[pcur];
            unsigned long long acc[32];
#pragma unroll
            for (int e = 0; e < 32; e++) acc[e] = 0ull;
#pragma unroll
            for (int j = 0; j < 2; j++) {
                const int k = sZ * 4 + j * 256;
#pragma unroll
                for (int i = 0; i < 8; i++) {
                    double2 av = *(const double2*)&ap[i * H_S + k];
                    unsigned long long a0 = __double_as_longlong(av.x);
                    unsigned long long a1 = __double_as_longlong(av.y);
#pragma unroll
                    for (int c = 0; c < 4; c++) {
                        fma2(acc[i * 4 + c], a0, wt1[j][c][0]);
                        fma2(acc[i * 4 + c], a1, wt1[j][c][1]);
                    }
                }
            }
#pragma unroll
            for (int i = 0; i < 8; i++)
#pragma unroll
                for (int c = 0; c < 4; c++)
                    sm[P_SCRA + sZ * S1_S + i * 16 + tcZ + c] = pair_sum(acc[i * 4 + c]);
        }
        __syncthreads();                   // #1: SCRA visible to reducers

        // ---- z1 reduce + relu + DSMEM push + remote arrives (warps 0-3);
        //      warps 4-7 fall straight through into A2 (separate scratch) ----
        if (tid < 128) {
            float a0 = 0.f, a1 = 0.f;
#pragma unroll
            for (int s = 0; s < 64; s += 2) {
                a0 += sm[P_SCRA + (s + 0) * S1_S + zr * 16 + zc];
                a1 += sm[P_SCRA + (s + 1) * S1_S + zr * 16 + zc];
            }
            float z = sm[P_B1 + zc] + xqv + (a0 + a1);
            z = fmaxf(z, 0.f);
            unsigned a = sbase + (unsigned)(P_Z1 + zr * Z1_S + zc0 + zc) * 4u;
#pragma unroll
            for (unsigned rk = 0; rk < CLUSTER; rk++) st_cluster(a, rk, z);
#pragma unroll
            for (unsigned rk = 0; rk < CLUSTER; rk++) mbar_arrive_cluster(mbar_z1, rk);
        }

        // ---- A2: drive partials (8r x 32c, k=512), reg-W, 8r x 4c, S=32 -> SCRB ----
        {
            const float* ap = &sm[pcur];
            unsigned long long acc[32];
#pragma unroll
            for (int e = 0; e < 32; e++) acc[e] = 0ull;
#pragma unroll
            for (int j = 0; j < 4; j++) {
                const int k = sA * 4 + j * 128;
#pragma unroll
                for (int i = 0; i < 8; i++) {
                    double2 av = *(const double2*)&ap[i * H_S + k];
                    unsigned long long a0 = __double_as_longlong(av.x);
                    unsigned long long a1 = __double_as_longlong(av.y);
#pragma unroll
                    for (int c = 0; c < 4; c++) {
                        fma2(acc[i * 4 + c], a0, wrec[j][c][0]);
                        fma2(acc[i * 4 + c], a1, wrec[j][c][1]);
                    }
                }
            }
#pragma unroll
            for (int i = 0; i < 8; i++) {
                float4 v;
                v.x = pair_sum(acc[i * 4 + 0]);
                v.y = pair_sum(acc[i * 4 + 1]);
                v.z = pair_sum(acc[i * 4 + 2]);
                v.w = pair_sum(acc[i * 4 + 3]);
                *(float4*)&sm[P_SCRB + sA * S2_S + i * 32 + tcA] = v;
            }
        }
        __syncthreads();                   // #2: SCRB visible to reducers

        // ---- drive reduce (32 partials, SCRB) -> tanh ----
        {
            float pre = xv + sm[P_BIAS + cc];
#pragma unroll
            for (int s = 0; s < 32; s++) pre += sm[P_SCRB + s * S2_S + tid];
            float e2 = __expf(2.f * pre);
            drv = 1.f - 2.f / (e2 + 1.f);
        }
        mbar_wait_parity(mbar_z1, parity); // z1 resident in local P_Z1

        // ---- B1: tau partials (8r x 32c, k=256), reg-W, 8r x 4c, S=32 -> SCRC ----
        {
            const float* ap = &sm[P_Z1];
            unsigned long long acc[32];
#pragma unroll
            for (int e = 0; e < 32; e++) acc[e] = 0ull;
#pragma unroll
            for (int j = 0; j < 2; j++) {
                const int k = sA * 4 + j * 128;
#pragma unroll
                for (int i = 0; i < 8; i++) {
                    double2 av = *(const double2*)&ap[i * Z1_S + k];
                    unsigned long long a0 = __double_as_longlong(av.x);
                    unsigned long long a1 = __double_as_longlong(av.y);
#pragma unroll
                    for (int c = 0; c < 4; c++) {
                        fma2(acc[i * 4 + c], a0, wt2[j][c][0]);
                        fma2(acc[i * 4 + c], a1, wt2[j][c][1]);
                    }
                }
            }
#pragma unroll
            for (int i = 0; i < 8; i++) {
                float4 v;
                v.x = pair_sum(acc[i * 4 + 0]);
                v.y = pair_sum(acc[i * 4 + 1]);
                v.z = pair_sum(acc[i * 4 + 2]);
                v.w = pair_sum(acc[i * 4 + 3]);
                *(float4*)&sm[P_SCRC + sA * S2_S + i * 32 + tcA] = v;
            }
        }
        __syncthreads();                   // #3: SCRC visible to reducers

        // ---- B2: tau reduce (SCRC) + Euler + DSMEM h push + remote arrives ----
        {
            float sv = sm[P_B2 + cc];
#pragma unroll
            for (int s = 0; s < 32; s++) sv += sm[P_SCRC + s * S2_S + tid];
            float sig = 1.f / (1.f + __expf(-sv));
            float tau = 5.f + sig * 45.f;
            float hold = sm[pcur + rr * H_S + hc0 + cc];
            float hnew = hold + (drv - hold) / tau;
            unsigned a = sbase + (unsigned)(pnext + rr * H_S + hc0 + cc) * 4u;
#pragma unroll
            for (unsigned rk = 0; rk < CLUSTER; rk++) st_cluster(a, rk, hnew);
#pragma unroll
            for (unsigned rk = 0; rk < CLUSTER; rk++) mbar_arrive_cluster(mbar_h, rk);
            __stcg(&g_hs[((size_t)(r0 + rr) * T_ + t) * H_ + hc0 + cc], hnew);
        }
        {
            int tn = (t + 1 < T_) ? t + 1 : t;          // prefetch next step
            xv = __ldcg(&g_xp[((size_t)(r0 + rr) * T_ + tn) * H_ + hc0 + cc]);
            if (tid < 128)
                xqv = __ldcg(&g_xq[((size_t)(r0 + zr) * T_ + tn) * 256 + zc0 + zc]);
        }
        mbar_wait_parity(mbar_h, parity);  // h(t+1) resident in pnext
    }

    CLUSTER_SYNC();   // keep CTAs alive until all remote traffic landed
}

// ---------------- out = hs @ W_out + b_out ----------------------------------
__global__ void __launch_bounds__(256) out_gemm(const float* __restrict__ W_out,
                                                const float* __restrict__ b_out,
                                                float* __restrict__ out) {
    __shared__ float sw[H_ * 10];
    __shared__ float sb[10];
    for (int e = threadIdx.x; e < H_ * 10; e += 256) sw[e] = W_out[e];
    if (threadIdx.x < 10) sb[threadIdx.x] = b_out[threadIdx.x];
    __syncthreads();

    int wid = threadIdx.x >> 5, lane = threadIdx.x & 31;
    for (int row = blockIdx.x * 8 + wid; row < B_ * T_; row += gridDim.x * 8) {
        float h[16];
        const float* hp = &g_hs[(size_t)row * H_ + lane * 16];
#pragma unroll
        for (int i = 0; i < 4; i++) {
            float4 v = *(const float4*)&hp[i * 4];
            h[i * 4 + 0] = v.x; h[i * 4 + 1] = v.y;
            h[i * 4 + 2] = v.z; h[i * 4 + 3] = v.w;
        }
#pragma unroll
        for (int o = 0; o < 10; o++) {
            float p = 0.f;
#pragma unroll
            for (int i = 0; i < 16; i++) p += h[i] * sw[(lane * 16 + i) * 10 + o];
            p += __shfl_xor_sync(0xffffffff, p, 16);
            p += __shfl_xor_sync(0xffffffff, p, 8);
            p += __shfl_xor_sync(0xffffffff, p, 4);
            p += __shfl_xor_sync(0xffffffff, p, 2);
            p += __shfl_xor_sync(0xffffffff, p, 1);
            if (lane == 0) out[row * 10 + o] = p + sb[o];
        }
    }
}

// ---------------- launch -----------------------------------------------------
extern "C" void kernel_launch(void* const* d_in, const int* in_sizes, int n_in,
                              void* d_out, int out_size) {
    const float* x      = (const float*)d_in[0];
    const float* W_in   = (const float*)d_in[1];
    const float* b_in   = (const float*)d_in[2];
    const float* W_rec  = (const float*)d_in[3];
    const float* bias   = (const float*)d_in[4];
    const float* W_tau1 = (const float*)d_in[5];
    const float* b_tau1 = (const float*)d_in[6];
    const float* W_tau2 = (const float*)d_in[7];
    const float* b_tau2 = (const float*)d_in[8];
    const float* W_out  = (const float*)d_in[9];
    const float* b_out  = (const float*)d_in[10];
    float* out = (float*)d_out;

    float* d_xp; cudaGetSymbolAddress((void**)&d_xp, g_xp);
    float* d_xq; cudaGetSymbolAddress((void**)&d_xq, g_xq);
    float* d_weff; cudaGetSymbolAddress((void**)&d_weff, g_weff);
    float* d_beff; cudaGetSymbolAddress((void**)&d_beff, g_beff);

    cudaFuncSetAttribute(proj_gemm<H_>, cudaFuncAttributeMaxDynamicSharedMemorySize, XP_SMEM);
    cudaFuncSetAttribute(proj_gemm<256>, cudaFuncAttributeMaxDynamicSharedMemorySize, XP_SMEM);
    cudaFuncSetAttribute(scan_kernel, cudaFuncAttributeMaxDynamicSharedMemorySize, SCAN_SMEM);
    cudaFuncSetAttribute(scan_kernel, cudaFuncAttributeNonPortableClusterSizeAllowed, 1);

    weff_gemm<<<dim3(4, 2), 256>>>(W_in, W_tau1);
    beff_kernel<<<256, 64>>>(b_in, W_tau1, b_tau1);
    proj_gemm<H_><<<dim3(8, 1024), 256, XP_SMEM>>>(x, W_in, b_in, d_xp);
    proj_gemm<256><<<dim3(4, 1024), 256, XP_SMEM>>>(x, d_weff, d_beff, d_xq);
    scan_kernel<<<GRID_SCAN, NT, SCAN_SMEM>>>(W_rec, bias, W_tau1, b_tau1,
                                              W_tau2, b_tau2);
    out_gemm<<<2048, 256>>>(W_out, b_out, out);
}